// round 1
// baseline (speedup 1.0000x reference)
#include <cuda_runtime.h>

#define Bc 8
#define Cc 64
#define Occ 64
#define Hc 160
#define Wc 160
#define HWc (Hc*Wc)

// scratch (no allocations allowed)
__device__ float g_offset[Bc*18*HWc];   // conv offset output
__device__ float g_wT[9*64*64];         // w_dcn transposed to [k][c][o]
__device__ float g_inv[64];
__device__ float g_bias2[64];

// ---------------------------------------------------------------------------
// prep: transpose weights, fold BN
// ---------------------------------------------------------------------------
__global__ void prep_kernel(const float* __restrict__ w_dcn,
                            const float* __restrict__ b_dcn,
                            const float* __restrict__ gamma,
                            const float* __restrict__ beta,
                            const float* __restrict__ run_mean,
                            const float* __restrict__ run_var) {
    int t = threadIdx.x;
    for (int i = t; i < 9*64*64; i += 256) {
        int k = i >> 12; int r = i & 4095; int c = r >> 6; int o = r & 63;
        g_wT[i] = w_dcn[o*576 + c*9 + k];
    }
    if (t < 64) {
        float iv = gamma[t] * rsqrtf(run_var[t] + 1e-5f);
        g_inv[t] = iv;
        g_bias2[t] = b_dcn[t]*iv + beta[t] - run_mean[t]*iv;
    }
}

// ---------------------------------------------------------------------------
// offset conv: 3x3, 64 -> 18, zero pad. Thread: 4 consecutive w pixels, all
// 18 output channels in registers. Weights staged in smem, broadcast reads.
// ---------------------------------------------------------------------------
__global__ __launch_bounds__(256) void offset_conv_kernel(
        const float* __restrict__ x,
        const float* __restrict__ w_off,
        const float* __restrict__ b_off) {
    __shared__ float s_w[64*9*20];   // [c*9+tap][20], first 18 entries used
    int t = threadIdx.x;
    for (int i = t; i < 18*64*9; i += 256) {
        int oc = i / 576; int r = i % 576;      // r = c*9+tap
        s_w[r*20 + oc] = w_off[i];
    }
    __syncthreads();

    int gid = blockIdx.x*256 + t;
    int b   = gid / (Hc*40);
    int rem = gid % (Hc*40);
    int h   = rem / 40;
    int w0  = (rem % 40) * 4;

    float acc[18][4];
    #pragma unroll
    for (int oc = 0; oc < 18; oc++) {
        float bo = b_off[oc];
        #pragma unroll
        for (int j = 0; j < 4; j++) acc[oc][j] = bo;
    }

    const float* xb = x + (size_t)b*Cc*HWc;
    for (int c = 0; c < 64; c++) {
        const float* xc = xb + c*HWc;
        float xr[3][6];
        #pragma unroll
        for (int r = 0; r < 3; r++) {
            int hy = h + r - 1;
            bool vh = (hy >= 0) && (hy < Hc);
            #pragma unroll
            for (int j = 0; j < 6; j++) {
                int wx = w0 + j - 1;
                bool v = vh && (wx >= 0) && (wx < Wc);
                xr[r][j] = v ? xc[hy*Wc + wx] : 0.f;
            }
        }
        #pragma unroll
        for (int tap = 0; tap < 9; tap++) {
            const int ky = tap/3, kx = tap%3;
            float wr[18];
            const float* wp = s_w + (c*9 + tap)*20;
            *(float4*)&wr[0]   = *(const float4*)(wp + 0);
            *(float4*)&wr[4]   = *(const float4*)(wp + 4);
            *(float4*)&wr[8]   = *(const float4*)(wp + 8);
            *(float4*)&wr[12]  = *(const float4*)(wp + 12);
            *(float2*)&wr[16]  = *(const float2*)(wp + 16);
            #pragma unroll
            for (int oc = 0; oc < 18; oc++) {
                #pragma unroll
                for (int j = 0; j < 4; j++)
                    acc[oc][j] += wr[oc] * xr[ky][kx + j];
            }
        }
    }
    #pragma unroll
    for (int oc = 0; oc < 18; oc++) {
        float4 r4 = make_float4(acc[oc][0], acc[oc][1], acc[oc][2], acc[oc][3]);
        *(float4*)&g_offset[(((size_t)b*18 + oc)*Hc + h)*Wc + w0] = r4;
    }
}

// ---------------------------------------------------------------------------
// fused: deform bilinear sampling + 64x64x(9*64) contraction + BN + ReLU
// Block = 64 pixels (2 rows x 32 cols) of one image, 256 threads.
// Per k: stage s[c][p] (64x64, padded to 68) and w_k[c][o] (64x64) in smem;
// each thread accumulates a 4o x 4p register tile (2x LDS.128 per 16 FFMA).
// ---------------------------------------------------------------------------
__global__ __launch_bounds__(256) void main_kernel(
        const float* __restrict__ x,
        float* __restrict__ out) {
    __shared__ float s_s[64*68];
    __shared__ float s_w[64*64];
    __shared__ float s_wt[4][64];
    __shared__ int   s_idx[4][64];

    const int t  = threadIdx.x;
    const int b  = blockIdx.z;
    const int h0 = blockIdx.y * 2;
    const int w0 = blockIdx.x * 32;

    const int o0 = (t >> 4) * 4;       // output-channel tile base
    const int p0 = (t & 15) * 4;       // pixel tile base
    const int cc = t >> 2;             // channel for sampling
    const int pp = t & 3;

    float acc[4][4] = {};

    const float* xb = x + ((size_t)b*64 + cc)*HWc;

    for (int k = 0; k < 9; k++) {
        __syncthreads();   // prev GEMM done reading s_s / s_w

        // stage this k's weight slice via registers
        float wtmp[16];
        #pragma unroll
        for (int i = 0; i < 16; i++) wtmp[i] = g_wT[k*4096 + t + 256*i];

        // per-pixel bilinear metadata for this k (threads 0..63)
        if (t < 64) {
            int p = t, ph = p >> 5, pw = p & 31;
            int h = h0 + ph, w = w0 + pw;
            float oy = g_offset[(((size_t)b*18 + 2*k    )*Hc + h)*Wc + w];
            float ox = g_offset[(((size_t)b*18 + 2*k + 1)*Hc + h)*Wc + w];
            float py = (float)(h + k/3 - 1) + oy;
            float px = (float)(w + k%3 - 1) + ox;
            float y0 = floorf(py), x0 = floorf(px);
            #pragma unroll
            for (int d = 0; d < 4; d++) {
                float iy = y0 + (float)(d >> 1);
                float ix = x0 + (float)(d & 1);
                float wgt = (1.f - fabsf(py - iy)) * (1.f - fabsf(px - ix));
                bool valid = (iy >= 0.f) && (iy <= (float)(Hc-1)) &&
                             (ix >= 0.f) && (ix <= (float)(Wc-1));
                s_wt[d][p] = valid ? wgt : 0.f;
                int iyc = min(max((int)iy, 0), Hc-1);
                int ixc = min(max((int)ix, 0), Wc-1);
                s_idx[d][p] = iyc*Wc + ixc;
            }
        }
        #pragma unroll
        for (int i = 0; i < 16; i++) s_w[t + 256*i] = wtmp[i];
        __syncthreads();

        // sampling: each thread produces 16 samples for its channel cc
        #pragma unroll
        for (int j = 0; j < 16; j++) {
            int p = pp + 4*j;
            float v = s_wt[0][p]*xb[s_idx[0][p]] + s_wt[1][p]*xb[s_idx[1][p]]
                    + s_wt[2][p]*xb[s_idx[2][p]] + s_wt[3][p]*xb[s_idx[3][p]];
            s_s[cc*68 + p] = v;
        }
        __syncthreads();

        // GEMM accumulate over c
        #pragma unroll 8
        for (int c = 0; c < 64; c++) {
            float4 sv = *(const float4*)(s_s + c*68 + p0);
            float4 wv = *(const float4*)(s_w + c*64 + o0);
            float sa[4] = {sv.x, sv.y, sv.z, sv.w};
            float wa[4] = {wv.x, wv.y, wv.z, wv.w};
            #pragma unroll
            for (int i = 0; i < 4; i++)
                #pragma unroll
                for (int j = 0; j < 4; j++)
                    acc[i][j] += wa[i] * sa[j];
        }
    }

    // epilogue: BN fold + ReLU, vectorized store (4 consecutive w per tile row)
    const int ph = p0 >> 5, pw = p0 & 31;
    #pragma unroll
    for (int i = 0; i < 4; i++) {
        int o = o0 + i;
        float iv = g_inv[o], bs = g_bias2[o];
        float4 r;
        r.x = fmaxf(acc[i][0]*iv + bs, 0.f);
        r.y = fmaxf(acc[i][1]*iv + bs, 0.f);
        r.z = fmaxf(acc[i][2]*iv + bs, 0.f);
        r.w = fmaxf(acc[i][3]*iv + bs, 0.f);
        *(float4*)&out[(((size_t)b*64 + o)*Hc + h0 + ph)*Wc + w0 + pw] = r;
    }
}

// ---------------------------------------------------------------------------
extern "C" void kernel_launch(void* const* d_in, const int* in_sizes, int n_in,
                              void* d_out, int out_size) {
    const float* x        = (const float*)d_in[0];
    const float* w_off    = (const float*)d_in[1];
    const float* b_off    = (const float*)d_in[2];
    const float* w_dcn    = (const float*)d_in[3];
    const float* b_dcn    = (const float*)d_in[4];
    const float* gamma    = (const float*)d_in[5];
    const float* beta     = (const float*)d_in[6];
    const float* run_mean = (const float*)d_in[7];
    const float* run_var  = (const float*)d_in[8];
    float* out = (float*)d_out;

    prep_kernel<<<1, 256>>>(w_dcn, b_dcn, gamma, beta, run_mean, run_var);
    offset_conv_kernel<<<(Bc*Hc*40 + 255)/256, 256>>>(x, w_off, b_off);
    dim3 grid(Wc/32, Hc/2, Bc);
    main_kernel<<<grid, 256>>>(x, out);
}

// round 3
// speedup vs baseline: 1.8872x; 1.8872x over previous
#include <cuda_runtime.h>

#define Bc 8
#define Hc 160
#define Wc 160
#define HWc (Hc*Wc)

// scratch (no allocations allowed)
__device__ float g_offset[Bc*18*HWc];          // offset conv output
__device__ float g_xt[(size_t)Bc*HWc*64];      // x transposed to [b][hw][c]
__device__ float g_wT2[9*64*64];               // w_dcn as [k][o][c]
__device__ float g_inv[64];
__device__ float g_bias2[64];

#define FMA2(d,a,b) asm("fma.rn.f32x2 %0, %1, %2, %0;" : "+l"(d) : "l"(a), "l"(b))

// ---------------------------------------------------------------------------
// prep: transpose weights to [k][o][c], fold BN. grid = 9 blocks (one per k).
// ---------------------------------------------------------------------------
__global__ void prep_kernel(const float* __restrict__ w_dcn,
                            const float* __restrict__ b_dcn,
                            const float* __restrict__ gamma,
                            const float* __restrict__ beta,
                            const float* __restrict__ run_mean,
                            const float* __restrict__ run_var) {
    int k = blockIdx.x;
    int t = threadIdx.x;
    for (int i = t; i < 4096; i += 256) {
        int o = i >> 6, c = i & 63;
        g_wT2[k*4096 + i] = w_dcn[o*576 + c*9 + k];
    }
    if (k == 0 && t < 64) {
        float iv = gamma[t] * rsqrtf(run_var[t] + 1e-5f);
        g_inv[t] = iv;
        g_bias2[t] = b_dcn[t]*iv + beta[t] - run_mean[t]*iv;
    }
}

// ---------------------------------------------------------------------------
// transpose x: [b][c][hw] -> [b][hw][c]
// ---------------------------------------------------------------------------
__global__ __launch_bounds__(256) void transpose_kernel(const float* __restrict__ x) {
    __shared__ float sm[64*65];
    int b   = blockIdx.y;
    int hw0 = blockIdx.x * 64;
    int t   = threadIdx.x;
    const float* xb = x + (size_t)b*64*HWc;
    #pragma unroll
    for (int i = 0; i < 16; i++) {
        int c = i*4 + (t>>6);
        int j = t & 63;
        sm[c*65 + j] = xb[(size_t)c*HWc + hw0 + j];
    }
    __syncthreads();
    float* ob = g_xt + ((size_t)b*HWc + hw0)*64;
    #pragma unroll
    for (int i = 0; i < 16; i++) {
        int hw = i*4 + (t>>6);
        int c  = t & 63;
        ob[hw*64 + c] = sm[c*65 + hw];
    }
}

// ---------------------------------------------------------------------------
// offset conv: 3x3, 64 -> 18, zero pad (unchanged from round 1)
// ---------------------------------------------------------------------------
__global__ __launch_bounds__(256) void offset_conv_kernel(
        const float* __restrict__ x,
        const float* __restrict__ w_off,
        const float* __restrict__ b_off) {
    __shared__ float s_w[64*9*20];
    int t = threadIdx.x;
    for (int i = t; i < 18*64*9; i += 256) {
        int oc = i / 576; int r = i % 576;
        s_w[r*20 + oc] = w_off[i];
    }
    __syncthreads();

    int gid = blockIdx.x*256 + t;
    int b   = gid / (Hc*40);
    int rem = gid % (Hc*40);
    int h   = rem / 40;
    int w0  = (rem % 40) * 4;

    float acc[18][4];
    #pragma unroll
    for (int oc = 0; oc < 18; oc++) {
        float bo = b_off[oc];
        #pragma unroll
        for (int j = 0; j < 4; j++) acc[oc][j] = bo;
    }

    const float* xb = x + (size_t)b*64*HWc;
    for (int c = 0; c < 64; c++) {
        const float* xc = xb + (size_t)c*HWc;
        float xr[3][6];
        #pragma unroll
        for (int r = 0; r < 3; r++) {
            int hy = h + r - 1;
            bool vh = (hy >= 0) && (hy < Hc);
            #pragma unroll
            for (int j = 0; j < 6; j++) {
                int wx = w0 + j - 1;
                bool v = vh && (wx >= 0) && (wx < Wc);
                xr[r][j] = v ? xc[hy*Wc + wx] : 0.f;
            }
        }
        #pragma unroll
        for (int tap = 0; tap < 9; tap++) {
            const int ky = tap/3, kx = tap%3;
            float wr[18];
            const float* wp = s_w + (c*9 + tap)*20;
            *(float4*)&wr[0]   = *(const float4*)(wp + 0);
            *(float4*)&wr[4]   = *(const float4*)(wp + 4);
            *(float4*)&wr[8]   = *(const float4*)(wp + 8);
            *(float4*)&wr[12]  = *(const float4*)(wp + 12);
            *(float2*)&wr[16]  = *(const float2*)(wp + 16);
            #pragma unroll
            for (int oc = 0; oc < 18; oc++) {
                #pragma unroll
                for (int j = 0; j < 4; j++)
                    acc[oc][j] += wr[oc] * xr[ky][kx + j];
            }
        }
    }
    #pragma unroll
    for (int oc = 0; oc < 18; oc++) {
        float4 r4 = make_float4(acc[oc][0], acc[oc][1], acc[oc][2], acc[oc][3]);
        *(float4*)&g_offset[(((size_t)b*18 + oc)*Hc + h)*Wc + w0] = r4;
    }
}

// ---------------------------------------------------------------------------
// fused: deform bilinear sampling (channel-last) + 64x64x576 contraction
// + BN + ReLU.  Block = 64 pixels (2x32), 256 threads.
// Samples smem layout: s_s[p][c], XOR swizzle on c-quad: group = (c>>2) ^ ((p>>2)&15)
// Weights smem layout: s_w[o][c].
// GEMM: c-paired fma.rn.f32x2; thread tile 4o x 4p.
// ---------------------------------------------------------------------------
__global__ __launch_bounds__(256, 2) void main_kernel(float* __restrict__ out) {
    __shared__ float s_w[64*64];
    __shared__ float s_s[64*64];
    __shared__ float s_wt[4][64];
    __shared__ int   s_idx[4][64];

    const int t  = threadIdx.x;
    const int b  = blockIdx.z;
    const int h0 = blockIdx.y * 2;
    const int w0 = blockIdx.x * 32;

    const int o0 = (t >> 4) * 4;
    const int p0 = (t & 15) * 4;
    const int pg = t & 15;          // (p0+j)>>2 for j in 0..3
    const int sq = t & 15;          // sampling channel-quad
    const int sp = t >> 4;          // sampling pixel row (0..15)

    unsigned long long acc2[4][4];
    #pragma unroll
    for (int i = 0; i < 4; i++)
        #pragma unroll
        for (int j = 0; j < 4; j++) acc2[i][j] = 0ull;

    const float* xtb = g_xt + (size_t)b*HWc*64;

    for (int k = 0; k < 9; k++) {
        __syncthreads();    // previous GEMM done reading s_s/s_w/meta

        // stage this k's weight slice [o][c] via registers
        float wtmp[16];
        #pragma unroll
        for (int i = 0; i < 16; i++) wtmp[i] = g_wT2[k*4096 + t + 256*i];

        // per-pixel bilinear metadata for this k (threads 0..63)
        if (t < 64) {
            int p = t, ph = p >> 5, pw = p & 31;
            int h = h0 + ph, w = w0 + pw;
            float oy = g_offset[(((size_t)b*18 + 2*k    )*Hc + h)*Wc + w];
            float ox = g_offset[(((size_t)b*18 + 2*k + 1)*Hc + h)*Wc + w];
            float py = (float)(h + k/3 - 1) + oy;
            float px = (float)(w + k%3 - 1) + ox;
            float y0 = floorf(py), x0 = floorf(px);
            #pragma unroll
            for (int d = 0; d < 4; d++) {
                float iy = y0 + (float)(d >> 1);
                float ix = x0 + (float)(d & 1);
                float wgt = (1.f - fabsf(py - iy)) * (1.f - fabsf(px - ix));
                bool valid = (iy >= 0.f) && (iy <= (float)(Hc-1)) &&
                             (ix >= 0.f) && (ix <= (float)(Wc-1));
                s_wt[d][p] = valid ? wgt : 0.f;
                int iyc = min(max((int)iy, 0), Hc-1);
                int ixc = min(max((int)ix, 0), Wc-1);
                s_idx[d][p] = iyc*Wc + ixc;
            }
        }
        #pragma unroll
        for (int i = 0; i < 16; i++) s_w[t + 256*i] = wtmp[i];
        __syncthreads();

        // sampling: channel-last contiguous LDG.128 gathers
        #pragma unroll
        for (int pi = 0; pi < 4; pi++) {
            int p = pi*16 + sp;
            float ax = 0.f, ay = 0.f, az = 0.f, aw = 0.f;
            #pragma unroll
            for (int d = 0; d < 4; d++) {
                float wgt = s_wt[d][p];
                const float4 v = *(const float4*)(xtb + (size_t)s_idx[d][p]*64 + sq*4);
                ax += wgt*v.x; ay += wgt*v.y; az += wgt*v.z; aw += wgt*v.w;
            }
            *(float4*)&s_s[p*64 + 4*(sq ^ ((p >> 2) & 15))] =
                make_float4(ax, ay, az, aw);
        }
        __syncthreads();

        // GEMM: 16 c-quads, f32x2 packed FMAs
        #pragma unroll 8
        for (int c4 = 0; c4 < 16; c4++) {
            ulonglong2 av[4], wv[4];
            #pragma unroll
            for (int j = 0; j < 4; j++)
                av[j] = *(const ulonglong2*)&s_s[(p0 + j)*64 + 4*(c4 ^ pg)];
            #pragma unroll
            for (int i = 0; i < 4; i++)
                wv[i] = *(const ulonglong2*)&s_w[(o0 + i)*64 + c4*4];
            #pragma unroll
            for (int i = 0; i < 4; i++)
                #pragma unroll
                for (int j = 0; j < 4; j++) {
                    FMA2(acc2[i][j], wv[i].x, av[j].x);
                    FMA2(acc2[i][j], wv[i].y, av[j].y);
                }
        }
    }

    // epilogue: reduce f32x2 pairs, BN fold + ReLU, vectorized store
    const int ph = p0 >> 5, pw = p0 & 31;
    #pragma unroll
    for (int i = 0; i < 4; i++) {
        int o = o0 + i;
        float iv = g_inv[o], bs = g_bias2[o];
        float v[4];
        #pragma unroll
        for (int j = 0; j < 4; j++) {
            float lo = __uint_as_float((unsigned)(acc2[i][j] & 0xffffffffull));
            float hi = __uint_as_float((unsigned)(acc2[i][j] >> 32));
            v[j] = lo + hi;
        }
        float4 r;
        r.x = fmaxf(v[0]*iv + bs, 0.f);
        r.y = fmaxf(v[1]*iv + bs, 0.f);
        r.z = fmaxf(v[2]*iv + bs, 0.f);
        r.w = fmaxf(v[3]*iv + bs, 0.f);
        *(float4*)&out[(((size_t)b*64 + o)*Hc + h0 + ph)*Wc + w0 + pw] = r;
    }
}

// ---------------------------------------------------------------------------
extern "C" void kernel_launch(void* const* d_in, const int* in_sizes, int n_in,
                              void* d_out, int out_size) {
    const float* x        = (const float*)d_in[0];
    const float* w_off    = (const float*)d_in[1];
    const float* b_off    = (const float*)d_in[2];
    const float* w_dcn    = (const float*)d_in[3];
    const float* b_dcn    = (const float*)d_in[4];
    const float* gamma    = (const float*)d_in[5];
    const float* beta     = (const float*)d_in[6];
    const float* run_mean = (const float*)d_in[7];
    const float* run_var  = (const float*)d_in[8];
    float* out = (float*)d_out;

    prep_kernel<<<9, 256>>>(w_dcn, b_dcn, gamma, beta, run_mean, run_var);
    transpose_kernel<<<dim3(HWc/64, Bc), 256>>>(x);
    offset_conv_kernel<<<(Bc*Hc*40 + 255)/256, 256>>>(x, w_off, b_off);
    dim3 grid(Wc/32, Hc/2, Bc);
    main_kernel<<<grid, 256>>>(out);
}

// round 4
// speedup vs baseline: 1.9674x; 1.0425x over previous
#include <cuda_runtime.h>

#define Bc 8
#define Hc 160
#define Wc 160
#define HWc (Hc*Wc)

typedef unsigned long long ull;

// scratch (no allocations allowed)
__device__ float g_offset[Bc*18*HWc];          // offset conv output
__device__ float g_xt[(size_t)Bc*HWc*64];      // x transposed to [b][hw][c]
__device__ float g_wT[9*64*64];                // w_dcn as [k][c][o]
__device__ float g_inv[64];
__device__ float g_bias2[64];

#define FMA2(d,a,b) asm("fma.rn.f32x2 %0, %1, %2, %0;" : "+l"(d) : "l"(a), "l"(b))
#define FMA2O(y,a,b,c) asm("fma.rn.f32x2 %0, %1, %2, %3;" : "=l"(y) : "l"(a), "l"(b), "l"(c))
#define DUP(d,s)  asm("mov.b64 %0, {%1,%1};" : "=l"(d) : "f"(s))
#define PACK2(d,lo,hi) asm("mov.b64 %0, {%1,%2};" : "=l"(d) : "f"(lo), "f"(hi))

// ---------------------------------------------------------------------------
// prep: transpose weights to [k][c][o], fold BN
// ---------------------------------------------------------------------------
__global__ void prep_kernel(const float* __restrict__ w_dcn,
                            const float* __restrict__ b_dcn,
                            const float* __restrict__ gamma,
                            const float* __restrict__ beta,
                            const float* __restrict__ run_mean,
                            const float* __restrict__ run_var) {
    int k = blockIdx.x;
    int t = threadIdx.x;
    for (int i = t; i < 4096; i += 256) {
        int c = i >> 6, o = i & 63;
        g_wT[k*4096 + i] = w_dcn[o*576 + c*9 + k];
    }
    if (k == 0 && t < 64) {
        float iv = gamma[t] * rsqrtf(run_var[t] + 1e-5f);
        g_inv[t] = iv;
        g_bias2[t] = b_dcn[t]*iv + beta[t] - run_mean[t]*iv;
    }
}

// ---------------------------------------------------------------------------
// transpose x: [b][c][hw] -> [b][hw][c]
// ---------------------------------------------------------------------------
__global__ __launch_bounds__(256) void transpose_kernel(const float* __restrict__ x) {
    __shared__ float sm[64*65];
    int b   = blockIdx.y;
    int hw0 = blockIdx.x * 64;
    int t   = threadIdx.x;
    const float* xb = x + (size_t)b*64*HWc;
    #pragma unroll
    for (int i = 0; i < 16; i++) {
        int c = i*4 + (t>>6);
        int j = t & 63;
        sm[c*65 + j] = xb[(size_t)c*HWc + hw0 + j];
    }
    __syncthreads();
    float* ob = g_xt + ((size_t)b*HWc + hw0)*64;
    #pragma unroll
    for (int i = 0; i < 16; i++) {
        int hw = i*4 + (t>>6);
        int c  = t & 63;
        ob[hw*64 + c] = sm[c*65 + hw];
    }
}

// ---------------------------------------------------------------------------
// offset conv: 3x3, 64 -> 18, zero pad; f32x2 packed over output-channel pairs
// ---------------------------------------------------------------------------
__global__ __launch_bounds__(256, 2) void offset_conv_kernel(
        const float* __restrict__ x,
        const float* __restrict__ w_off,
        const float* __restrict__ b_off) {
    __shared__ float s_w[64*9*20];   // [c*9+tap][20], first 18 entries = oc
    int t = threadIdx.x;
    for (int i = t; i < 18*64*9; i += 256) {
        int oc = i / 576; int r = i % 576;
        s_w[r*20 + oc] = w_off[i];
    }
    __syncthreads();

    int gid = blockIdx.x*256 + t;
    int b   = gid / (Hc*40);
    int rem = gid % (Hc*40);
    int h   = rem / 40;
    int w0  = (rem % 40) * 4;

    ull acc2[9][4];
    #pragma unroll
    for (int i = 0; i < 9; i++) {
        ull bo2; PACK2(bo2, b_off[2*i], b_off[2*i+1]);
        #pragma unroll
        for (int j = 0; j < 4; j++) acc2[i][j] = bo2;
    }

    const float* xb = x + (size_t)b*64*HWc;
    for (int c = 0; c < 64; c++) {
        const float* xc = xb + (size_t)c*HWc;
        float xr[3][6];
        #pragma unroll
        for (int r = 0; r < 3; r++) {
            int hy = h + r - 1;
            bool vh = (hy >= 0) && (hy < Hc);
            #pragma unroll
            for (int j = 0; j < 6; j++) {
                int wx = w0 + j - 1;
                bool v = vh && (wx >= 0) && (wx < Wc);
                xr[r][j] = v ? xc[hy*Wc + wx] : 0.f;
            }
        }
        #pragma unroll
        for (int tap = 0; tap < 9; tap++) {
            const int ky = tap/3, kx = tap%3;
            const float* wp = s_w + (c*9 + tap)*20;
            ull wr2[9];
            {
                ulonglong2 q0 = *(const ulonglong2*)(wp + 0);
                ulonglong2 q1 = *(const ulonglong2*)(wp + 4);
                ulonglong2 q2 = *(const ulonglong2*)(wp + 8);
                ulonglong2 q3 = *(const ulonglong2*)(wp + 12);
                ull q4 = *(const ull*)(wp + 16);
                wr2[0]=q0.x; wr2[1]=q0.y; wr2[2]=q1.x; wr2[3]=q1.y;
                wr2[4]=q2.x; wr2[5]=q2.y; wr2[6]=q3.x; wr2[7]=q3.y; wr2[8]=q4;
            }
            #pragma unroll
            for (int j = 0; j < 4; j++) {
                ull xd; DUP(xd, xr[ky][kx + j]);
                #pragma unroll
                for (int i = 0; i < 9; i++)
                    FMA2(acc2[i][j], wr2[i], xd);
            }
        }
    }
    #pragma unroll
    for (int i = 0; i < 9; i++) {
        float4 rlo, rhi;
        float* plo = (float*)&rlo; float* phi = (float*)&rhi;
        #pragma unroll
        for (int j = 0; j < 4; j++) {
            plo[j] = __uint_as_float((unsigned)(acc2[i][j] & 0xffffffffull));
            phi[j] = __uint_as_float((unsigned)(acc2[i][j] >> 32));
        }
        *(float4*)&g_offset[(((size_t)b*18 + 2*i  )*Hc + h)*Wc + w0] = rlo;
        *(float4*)&g_offset[(((size_t)b*18 + 2*i+1)*Hc + h)*Wc + w0] = rhi;
    }
}

// ---------------------------------------------------------------------------
// fused: deform bilinear sampling (channel-last) + 64x64x576 contraction
// + BN + ReLU.
// Block = 256 pixels (8 rows x 32 cols), 256 threads, 64 outputs.
// Thread tile: 8o x 8p, f32x2 packed along pixel pairs.
// smem: s_s[c][257] samples (odd stride: sampler transpose stores 2-way max),
//       s_w2[c][2*o] weights pre-duplicated (w,w) for broadcast LDS.128.
// GEMM per c per warp: 8 scalar LDS.32 (consecutive lanes, 1 wf each)
//                      + 4 broadcast LDS.128 + 4 packs + 32 FFMA2.
// ---------------------------------------------------------------------------
#define SS_STRIDE 257
#define SMEM_SS   (64*SS_STRIDE)          // 16448 floats
#define SMEM_SW2  (SMEM_SS + 64*128)      // + 8192
#define SMEM_WT   (SMEM_SW2)              // s_wt starts here
#define SMEM_IDX  (SMEM_SW2 + 1024)
#define SMEM_FLOATS (SMEM_SW2 + 2048)

__global__ __launch_bounds__(256, 2) void main_kernel(float* __restrict__ out) {
    extern __shared__ float smem[];
    float* s_s  = smem;                    // [64][257]
    float* s_w2 = smem + SMEM_SS;          // [64][128] dup pairs
    float* s_wt = smem + SMEM_SW2 + 0;     // [4][256] -- NOTE: see below
    int*   s_idx;

    // real layout: s_w2 then s_wt then s_idx
    s_wt  = smem + SMEM_SS + 64*128;
    s_idx = (int*)(smem + SMEM_SS + 64*128 + 4*256);

    const int t    = threadIdx.x;
    const int b    = blockIdx.z;
    const int h0   = blockIdx.y * 8;
    const int w0   = blockIdx.x * 32;
    const int lane = t & 31;
    const int o0   = (t >> 5) * 8;
    const int sq   = t & 15;          // sampler channel-quad
    const int pg   = t >> 4;          // sampler pixel phase (0..15)

    ull acc2[8][4];
    #pragma unroll
    for (int i = 0; i < 8; i++)
        #pragma unroll
        for (int j = 0; j < 4; j++) acc2[i][j] = 0ull;

    const float* xtb = g_xt + (size_t)b*HWc*64;

    #pragma unroll 1
    for (int k = 0; k < 9; k++) {
        __syncthreads();   // previous GEMM done reading smem

        // stage this k's weights (dup pairs) via registers
        float wtmp[16];
        #pragma unroll
        for (int i = 0; i < 16; i++) wtmp[i] = g_wT[k*4096 + i*256 + t];

        // per-pixel bilinear metadata (thread t = pixel t)
        {
            int p = t;
            int h = h0 + (p >> 5), w = w0 + (p & 31);
            float oy = g_offset[(((size_t)b*18 + 2*k    )*Hc + h)*Wc + w];
            float ox = g_offset[(((size_t)b*18 + 2*k + 1)*Hc + h)*Wc + w];
            float py = (float)(h + k/3 - 1) + oy;
            float px = (float)(w + k%3 - 1) + ox;
            float y0 = floorf(py), x0 = floorf(px);
            #pragma unroll
            for (int d = 0; d < 4; d++) {
                float iy = y0 + (float)(d >> 1);
                float ix = x0 + (float)(d & 1);
                float wgt = (1.f - fabsf(py - iy)) * (1.f - fabsf(px - ix));
                bool valid = (iy >= 0.f) && (iy <= (float)(Hc-1)) &&
                             (ix >= 0.f) && (ix <= (float)(Wc-1));
                s_wt[d*256 + p] = valid ? wgt : 0.f;
                int iyc = min(max((int)iy, 0), Hc-1);
                int ixc = min(max((int)ix, 0), Wc-1);
                s_idx[d*256 + p] = (iyc*Wc + ixc) * 64;   // channel-row offset
            }
        }
        #pragma unroll
        for (int i = 0; i < 16; i++) {
            int e = i*256 + t;
            int c = e >> 6, o = e & 63;
            float2 d2 = make_float2(wtmp[i], wtmp[i]);
            *(float2*)&s_w2[c*128 + o*2] = d2;
        }
        __syncthreads();

        // sampling: channel-last contiguous LDG.128 gathers, transpose store
        #pragma unroll 4
        for (int j = 0; j < 16; j++) {
            int p = pg + 16*j;
            float ax = 0.f, ay = 0.f, az = 0.f, aw = 0.f;
            #pragma unroll
            for (int d = 0; d < 4; d++) {
                float wg = s_wt[d*256 + p];
                const float4 v = *(const float4*)(xtb + (size_t)s_idx[d*256 + p] + sq*4);
                ax += wg*v.x; ay += wg*v.y; az += wg*v.z; aw += wg*v.w;
            }
            s_s[(4*sq+0)*SS_STRIDE + p] = ax;
            s_s[(4*sq+1)*SS_STRIDE + p] = ay;
            s_s[(4*sq+2)*SS_STRIDE + p] = az;
            s_s[(4*sq+3)*SS_STRIDE + p] = aw;
        }
        __syncthreads();

        // GEMM accumulate over c
        #pragma unroll 4
        for (int c = 0; c < 64; c++) {
            const float* row = s_s + c*SS_STRIDE + lane;
            float s0 = row[0],   s1 = row[32],  s2 = row[64],  s3 = row[96];
            float s4 = row[128], s5 = row[160], s6 = row[192], s7 = row[224];
            ull sp[4];
            PACK2(sp[0], s0, s1); PACK2(sp[1], s2, s3);
            PACK2(sp[2], s4, s5); PACK2(sp[3], s6, s7);
            const float* wr = s_w2 + c*128 + o0*2;
            ulonglong2 wv0 = *(const ulonglong2*)(wr + 0);
            ulonglong2 wv1 = *(const ulonglong2*)(wr + 4);
            ulonglong2 wv2 = *(const ulonglong2*)(wr + 8);
            ulonglong2 wv3 = *(const ulonglong2*)(wr + 12);
            ull wd[8] = {wv0.x, wv0.y, wv1.x, wv1.y, wv2.x, wv2.y, wv3.x, wv3.y};
            #pragma unroll
            for (int i = 0; i < 8; i++)
                #pragma unroll
                for (int j = 0; j < 4; j++)
                    FMA2(acc2[i][j], wd[i], sp[j]);
        }
    }

    // epilogue: BN fold + ReLU. acc2[i][j] = pixels (lane+64j, lane+64j+32), o = o0+i
    #pragma unroll
    for (int i = 0; i < 8; i++) {
        int o = o0 + i;
        ull ivd, bsd;
        DUP(ivd, g_inv[o]); DUP(bsd, g_bias2[o]);
        float* ob = out + (((size_t)b*64 + o)*Hc + h0)*Wc + w0 + lane;
        #pragma unroll
        for (int j = 0; j < 4; j++) {
            ull y; FMA2O(y, acc2[i][j], ivd, bsd);
            float lo = __uint_as_float((unsigned)(y & 0xffffffffull));
            float hi = __uint_as_float((unsigned)(y >> 32));
            ob[(2*j  )*Wc] = fmaxf(lo, 0.f);
            ob[(2*j+1)*Wc] = fmaxf(hi, 0.f);
        }
    }
}

// ---------------------------------------------------------------------------
extern "C" void kernel_launch(void* const* d_in, const int* in_sizes, int n_in,
                              void* d_out, int out_size) {
    const float* x        = (const float*)d_in[0];
    const float* w_off    = (const float*)d_in[1];
    const float* b_off    = (const float*)d_in[2];
    const float* w_dcn    = (const float*)d_in[3];
    const float* b_dcn    = (const float*)d_in[4];
    const float* gamma    = (const float*)d_in[5];
    const float* beta     = (const float*)d_in[6];
    const float* run_mean = (const float*)d_in[7];
    const float* run_var  = (const float*)d_in[8];
    float* out = (float*)d_out;

    const int smem_bytes = SMEM_FLOATS * 4;   // 106752 B
    static int configured = 0;
    if (!configured) {
        cudaFuncSetAttribute(main_kernel,
                             cudaFuncAttributeMaxDynamicSharedMemorySize,
                             smem_bytes);
        configured = 1;
    }

    prep_kernel<<<9, 256>>>(w_dcn, b_dcn, gamma, beta, run_mean, run_var);
    transpose_kernel<<<dim3(HWc/64, Bc), 256>>>(x);
    offset_conv_kernel<<<(Bc*Hc*40 + 255)/256, 256>>>(x, w_off, b_off);
    dim3 grid(Wc/32, Hc/8, Bc);
    main_kernel<<<grid, 256, smem_bytes>>>(out);
}

// round 6
// speedup vs baseline: 3.2738x; 1.6641x over previous
#include <cuda_runtime.h>
#include <cuda_bf16.h>
#include <cstdint>

#define Bc 8
#define Hc 160
#define Wc 160
#define HWc (Hc*Wc)

typedef unsigned long long ull;

// scratch (no allocations allowed)
__device__ float g_offset[Bc*18*HWc];            // offset conv output
__device__ float g_xt[(size_t)Bc*HWc*64];        // x transposed to [b][hw][c]
__device__ uint2 g_bfrag_hi[9*4*8*32];           // B frags bf16 hi [k][kstep][ntile][lane]
__device__ uint2 g_bfrag_lo[9*4*8*32];           // B frags bf16 lo
__device__ float g_inv[64];
__device__ float g_bias2[64];

#define FMA2(d,a,b) asm("fma.rn.f32x2 %0, %1, %2, %0;" : "+l"(d) : "l"(a), "l"(b))
#define DUP(d,s)  asm("mov.b64 %0, {%1,%1};" : "=l"(d) : "f"(s))
#define PACK2(d,lo,hi) asm("mov.b64 %0, {%1,%2};" : "=l"(d) : "f"(lo), "f"(hi))

__device__ __forceinline__ uint32_t smem_u32(const void* p) {
    uint32_t a;
    asm("{ .reg .u64 t; cvta.to.shared.u64 t, %1; cvt.u32.u64 %0, t; }" : "=r"(a) : "l"(p));
    return a;
}
__device__ __forceinline__ unsigned sw128(unsigned off) {
    return off ^ ((off >> 3) & 0x70);
}
__device__ __forceinline__ void ldsm4(uint32_t* r, uint32_t addr) {
    asm volatile("ldmatrix.sync.aligned.m8n8.x4.shared.b16 {%0,%1,%2,%3}, [%4];"
        : "=r"(r[0]), "=r"(r[1]), "=r"(r[2]), "=r"(r[3]) : "r"(addr));
}
__device__ __forceinline__ void mma16816(float* c, const uint32_t* a, const uint2 b) {
    asm volatile("mma.sync.aligned.m16n8k16.row.col.f32.bf16.bf16.f32 "
        "{%0,%1,%2,%3}, {%4,%5,%6,%7}, {%8,%9}, {%0,%1,%2,%3};"
        : "+f"(c[0]), "+f"(c[1]), "+f"(c[2]), "+f"(c[3])
        : "r"(a[0]), "r"(a[1]), "r"(a[2]), "r"(a[3]), "r"(b.x), "r"(b.y));
}
// pack (x,y) -> bf16x2 hi + residual bf16x2 lo
__device__ __forceinline__ void split2(float x, float y, uint32_t& hv, uint32_t& lv) {
    asm("cvt.rn.bf16x2.f32 %0, %1, %2;" : "=r"(hv) : "f"(y), "f"(x));   // high=y, low=x
    float hx = __uint_as_float(hv << 16);
    float hy = __uint_as_float(hv & 0xffff0000u);
    float rx = x - hx, ry = y - hy;
    asm("cvt.rn.bf16x2.f32 %0, %1, %2;" : "=r"(lv) : "f"(ry), "f"(rx));
}

// dynamic smem layout (bytes)
#define SM_A     0                         // samples hi: 256 rows x 128 B (SW128)
#define SM_ALO   32768                     // samples lo
#define SM_WT    65536                     // float[4][256]
#define SM_IDX   69632                     // int[4][256]
#define SM_TOTAL 73728

// ---------------------------------------------------------------------------
// prep: fold BN; split w_dcn to bf16 hi/lo directly in mma B-fragment layout.
// B frag (m16n8k16 col): lane holds b[k][n]: n = lane>>2, k = 2*(lane&3)+{0,1}
// (reg .x) and +8 (reg .y). k maps to input channel c, n to output o.
// ---------------------------------------------------------------------------
__global__ void prep_kernel(const float* __restrict__ w_dcn,
                            const float* __restrict__ b_dcn,
                            const float* __restrict__ gamma,
                            const float* __restrict__ beta,
                            const float* __restrict__ run_mean,
                            const float* __restrict__ run_var) {
    int k = blockIdx.x;
    int t = threadIdx.x;
    for (int e = t; e < 1024; e += 256) {
        int lane  = e & 31;
        int ntile = (e >> 5) & 7;
        int kstep = e >> 8;
        int o  = ntile*8 + (lane >> 2);
        int c0 = kstep*16 + 2*(lane & 3);
        float w00 = w_dcn[o*576 + (c0  )*9 + k];
        float w01 = w_dcn[o*576 + (c0+1)*9 + k];
        float w10 = w_dcn[o*576 + (c0+8)*9 + k];
        float w11 = w_dcn[o*576 + (c0+9)*9 + k];
        uint32_t h0, l0, h1, l1;
        split2(w00, w01, h0, l0);
        split2(w10, w11, h1, l1);
        int idx = ((k*4 + kstep)*8 + ntile)*32 + lane;
        g_bfrag_hi[idx] = make_uint2(h0, h1);
        g_bfrag_lo[idx] = make_uint2(l0, l1);
    }
    if (k == 0 && t < 64) {
        float iv = gamma[t] * rsqrtf(run_var[t] + 1e-5f);
        g_inv[t] = iv;
        g_bias2[t] = b_dcn[t]*iv + beta[t] - run_mean[t]*iv;
    }
}

// ---------------------------------------------------------------------------
// transpose x: [b][c][hw] -> [b][hw][c]
// ---------------------------------------------------------------------------
__global__ __launch_bounds__(256) void transpose_kernel(const float* __restrict__ x) {
    __shared__ float sm[64*65];
    int b   = blockIdx.y;
    int hw0 = blockIdx.x * 64;
    int t   = threadIdx.x;
    const float* xb = x + (size_t)b*64*HWc;
    #pragma unroll
    for (int i = 0; i < 16; i++) {
        int c = i*4 + (t>>6);
        int j = t & 63;
        sm[c*65 + j] = xb[(size_t)c*HWc + hw0 + j];
    }
    __syncthreads();
    float* ob = g_xt + ((size_t)b*HWc + hw0)*64;
    #pragma unroll
    for (int i = 0; i < 16; i++) {
        int hw = i*4 + (t>>6);
        int c  = t & 63;
        ob[hw*64 + c] = sm[c*65 + hw];
    }
}

// ---------------------------------------------------------------------------
// offset conv: 3x3, 64 -> 18, zero pad; f32x2 packed over output-channel pairs
// ---------------------------------------------------------------------------
__global__ __launch_bounds__(256, 2) void offset_conv_kernel(
        const float* __restrict__ x,
        const float* __restrict__ w_off,
        const float* __restrict__ b_off) {
    __shared__ float s_w[64*9*20];
    int t = threadIdx.x;
    for (int i = t; i < 18*64*9; i += 256) {
        int oc = i / 576; int r = i % 576;
        s_w[r*20 + oc] = w_off[i];
    }
    __syncthreads();

    int gid = blockIdx.x*256 + t;
    int b   = gid / (Hc*40);
    int rem = gid % (Hc*40);
    int h   = rem / 40;
    int w0  = (rem % 40) * 4;

    ull acc2[9][4];
    #pragma unroll
    for (int i = 0; i < 9; i++) {
        ull bo2; PACK2(bo2, b_off[2*i], b_off[2*i+1]);
        #pragma unroll
        for (int j = 0; j < 4; j++) acc2[i][j] = bo2;
    }

    const float* xb = x + (size_t)b*64*HWc;
    for (int c = 0; c < 64; c++) {
        const float* xc = xb + (size_t)c*HWc;
        float xr[3][6];
        #pragma unroll
        for (int r = 0; r < 3; r++) {
            int hy = h + r - 1;
            bool vh = (hy >= 0) && (hy < Hc);
            #pragma unroll
            for (int j = 0; j < 6; j++) {
                int wx = w0 + j - 1;
                bool v = vh && (wx >= 0) && (wx < Wc);
                xr[r][j] = v ? xc[hy*Wc + wx] : 0.f;
            }
        }
        #pragma unroll
        for (int tap = 0; tap < 9; tap++) {
            const int ky = tap/3, kx = tap%3;
            const float* wp = s_w + (c*9 + tap)*20;
            ull wr2[9];
            {
                ulonglong2 q0 = *(const ulonglong2*)(wp + 0);
                ulonglong2 q1 = *(const ulonglong2*)(wp + 4);
                ulonglong2 q2 = *(const ulonglong2*)(wp + 8);
                ulonglong2 q3 = *(const ulonglong2*)(wp + 12);
                ull q4 = *(const ull*)(wp + 16);
                wr2[0]=q0.x; wr2[1]=q0.y; wr2[2]=q1.x; wr2[3]=q1.y;
                wr2[4]=q2.x; wr2[5]=q2.y; wr2[6]=q3.x; wr2[7]=q3.y; wr2[8]=q4;
            }
            #pragma unroll
            for (int j = 0; j < 4; j++) {
                ull xd; DUP(xd, xr[ky][kx + j]);
                #pragma unroll
                for (int i = 0; i < 9; i++)
                    FMA2(acc2[i][j], wr2[i], xd);
            }
        }
    }
    #pragma unroll
    for (int i = 0; i < 9; i++) {
        float4 rlo, rhi;
        float* plo = (float*)&rlo; float* phi = (float*)&rhi;
        #pragma unroll
        for (int j = 0; j < 4; j++) {
            plo[j] = __uint_as_float((unsigned)(acc2[i][j] & 0xffffffffull));
            phi[j] = __uint_as_float((unsigned)(acc2[i][j] >> 32));
        }
        *(float4*)&g_offset[(((size_t)b*18 + 2*i  )*Hc + h)*Wc + w0] = rlo;
        *(float4*)&g_offset[(((size_t)b*18 + 2*i+1)*Hc + h)*Wc + w0] = rhi;
    }
}

// ---------------------------------------------------------------------------
// fused main: bilinear sampling -> bf16 hi/lo A tiles (SW128 smem) ->
// warp-level mma.sync bf16 (3-pass split, fp32 acc) -> BN + ReLU.
// Block = 256 px (8 rows x 32 cols) x 64 o; warp = 32 px x 64 o.
// ---------------------------------------------------------------------------
__global__ __launch_bounds__(256, 2) void main_kernel(float* __restrict__ out) {
    extern __shared__ char smem[];
    const uint32_t sbase = smem_u32(smem);
    float* s_wt  = (float*)(smem + SM_WT);
    int*   s_idx = (int*)(smem + SM_IDX);

    const int t    = threadIdx.x;
    const int wid  = t >> 5;
    const int lane = t & 31;
    const int b    = blockIdx.z;
    const int h0   = blockIdx.y * 8;
    const int w0   = blockIdx.x * 32;
    const int sq   = t & 15;       // sampler channel-quad
    const int pg   = t >> 4;       // sampler pixel phase (0..15)

    float acc[2][8][4];
    #pragma unroll
    for (int mt = 0; mt < 2; mt++)
        #pragma unroll
        for (int nt = 0; nt < 8; nt++)
            #pragma unroll
            for (int r = 0; r < 4; r++) acc[mt][nt][r] = 0.f;

    const float* xtb = g_xt + (size_t)b*HWc*64;

    // A-frag ldmatrix addresses (constant across phases / k-steps except kstep col)
    const int arow = wid*32 + (lane & 7) + ((lane >> 3) & 1)*8;   // + mt*16
    const int acol = (lane >> 4) * 16;                            // + kstep*32

    #pragma unroll 1
    for (int k = 0; k < 9; k++) {
        __syncthreads();   // previous phase's mma reads done

        // per-pixel bilinear metadata (thread t = pixel t)
        {
            int p = t;
            int h = h0 + (p >> 5), w = w0 + (p & 31);
            float oy = g_offset[(((size_t)b*18 + 2*k    )*Hc + h)*Wc + w];
            float ox = g_offset[(((size_t)b*18 + 2*k + 1)*Hc + h)*Wc + w];
            float py = (float)(h + k/3 - 1) + oy;
            float px = (float)(w + k%3 - 1) + ox;
            float y0 = floorf(py), x0 = floorf(px);
            #pragma unroll
            for (int d = 0; d < 4; d++) {
                float iy = y0 + (float)(d >> 1);
                float ix = x0 + (float)(d & 1);
                float wgt = (1.f - fabsf(py - iy)) * (1.f - fabsf(px - ix));
                bool valid = (iy >= 0.f) && (iy <= (float)(Hc-1)) &&
                             (ix >= 0.f) && (ix <= (float)(Wc-1));
                s_wt[d*256 + p] = valid ? wgt : 0.f;
                int iyc = min(max((int)iy, 0), Hc-1);
                int ixc = min(max((int)ix, 0), Wc-1);
                s_idx[d*256 + p] = (iyc*Wc + ixc) * 64;
            }
        }
        __syncthreads();

        // sampling: gather channel-last, split to bf16 hi/lo, store swizzled
        #pragma unroll 4
        for (int j = 0; j < 16; j++) {
            int p = pg + 16*j;
            float ax = 0.f, ay = 0.f, az = 0.f, aw = 0.f;
            #pragma unroll
            for (int d = 0; d < 4; d++) {
                float wg = s_wt[d*256 + p];
                const float4 v = *(const float4*)(xtb + (size_t)s_idx[d*256 + p] + sq*4);
                ax += wg*v.x; ay += wg*v.y; az += wg*v.z; aw += wg*v.w;
            }
            uint2 hv, lv;
            split2(ax, ay, hv.x, lv.x);
            split2(az, aw, hv.y, lv.y);
            unsigned sw = sw128((unsigned)(p*128 + sq*8));
            *(uint2*)(smem + SM_A   + sw) = hv;
            *(uint2*)(smem + SM_ALO + sw) = lv;
        }
        __syncthreads();

        // GEMM: per k-step load A hi/lo frags (ldmatrix) + B hi/lo frags (gmem),
        // issue 3-pass mma
        const uint2* bfh = g_bfrag_hi + (size_t)k*1024;
        const uint2* bfl = g_bfrag_lo + (size_t)k*1024;
        #pragma unroll
        for (int ks = 0; ks < 4; ks++) {
            uint32_t ah[2][4], al[2][4];
            #pragma unroll
            for (int mt = 0; mt < 2; mt++) {
                unsigned off = sw128((unsigned)((arow + mt*16)*128 + acol + ks*32));
                ldsm4(ah[mt], sbase + SM_A   + off);
                ldsm4(al[mt], sbase + SM_ALO + off);
            }
            uint2 bh[8], bl[8];
            #pragma unroll
            for (int nt = 0; nt < 8; nt++) {
                bh[nt] = __ldg(&bfh[(ks*8 + nt)*32 + lane]);
                bl[nt] = __ldg(&bfl[(ks*8 + nt)*32 + lane]);
            }
            #pragma unroll
            for (int mt = 0; mt < 2; mt++)
                #pragma unroll
                for (int nt = 0; nt < 8; nt++) {
                    mma16816(acc[mt][nt], ah[mt], bh[nt]);
                    mma16816(acc[mt][nt], al[mt], bh[nt]);
                    mma16816(acc[mt][nt], ah[mt], bl[nt]);
                }
        }
    }

    // epilogue: BN fold + ReLU, direct stores
    {
        const int prow = lane >> 2;
        const int ocol = 2*(lane & 3);
        #pragma unroll
        for (int nt = 0; nt < 8; nt++) {
            int o0 = nt*8 + ocol;
            float iv0 = g_inv[o0],   bs0 = g_bias2[o0];
            float iv1 = g_inv[o0+1], bs1 = g_bias2[o0+1];
            #pragma unroll
            for (int mt = 0; mt < 2; mt++) {
                #pragma unroll
                for (int half = 0; half < 2; half++) {
                    int p = wid*32 + mt*16 + prow + half*8;
                    int h = h0 + (p >> 5), w = w0 + (p & 31);
                    float* ob = out + ((size_t)b*64*Hc + h)*Wc + w;
                    float y0 = acc[mt][nt][half*2]   * iv0 + bs0;
                    float y1 = acc[mt][nt][half*2+1] * iv1 + bs1;
                    ob[(size_t)o0*HWc]     = fmaxf(y0, 0.f);
                    ob[(size_t)(o0+1)*HWc] = fmaxf(y1, 0.f);
                }
            }
        }
    }
}

// ---------------------------------------------------------------------------
extern "C" void kernel_launch(void* const* d_in, const int* in_sizes, int n_in,
                              void* d_out, int out_size) {
    const float* x        = (const float*)d_in[0];
    const float* w_off    = (const float*)d_in[1];
    const float* b_off    = (const float*)d_in[2];
    const float* w_dcn    = (const float*)d_in[3];
    const float* b_dcn    = (const float*)d_in[4];
    const float* gamma    = (const float*)d_in[5];
    const float* beta     = (const float*)d_in[6];
    const float* run_mean = (const float*)d_in[7];
    const float* run_var  = (const float*)d_in[8];
    float* out = (float*)d_out;

    cudaFuncSetAttribute(main_kernel,
                         cudaFuncAttributeMaxDynamicSharedMemorySize, SM_TOTAL);

    prep_kernel<<<9, 256>>>(w_dcn, b_dcn, gamma, beta, run_mean, run_var);
    transpose_kernel<<<dim3(HWc/64, Bc), 256>>>(x);
    offset_conv_kernel<<<(Bc*Hc*40 + 255)/256, 256>>>(x, w_off, b_off);
    dim3 grid(Wc/32, Hc/8, Bc);
    main_kernel<<<grid, 256, SM_TOTAL>>>(out);
}

// round 7
// speedup vs baseline: 3.8414x; 1.1734x over previous
#include <cuda_runtime.h>
#include <cuda_bf16.h>
#include <cstdint>

#define Bc 8
#define Hc 160
#define Wc 160
#define HWc (Hc*Wc)

typedef unsigned long long ull;

// scratch (no allocations allowed)
__device__ float g_offset[Bc*18*HWc];            // offset conv output
__device__ float g_xt[(size_t)Bc*HWc*64];        // x transposed to [b][hw][c]
__device__ uint2 g_bfrag_hi[9*4*8*32];           // main B frags bf16 hi [k][kstep][ntile][lane]
__device__ uint2 g_bfrag_lo[9*4*8*32];           // main B frags bf16 lo
__device__ uint2 g_bfragO_hi[9*4*3*32];          // offset-conv B frags hi [k][kstep][ntile][lane]
__device__ uint2 g_bfragO_lo[9*4*3*32];          // offset-conv B frags lo
__device__ float g_inv[64];
__device__ float g_bias2[64];

__device__ __forceinline__ uint32_t smem_u32(const void* p) {
    uint32_t a;
    asm("{ .reg .u64 t; cvta.to.shared.u64 t, %1; cvt.u32.u64 %0, t; }" : "=r"(a) : "l"(p));
    return a;
}
__device__ __forceinline__ unsigned sw128(unsigned off) {
    return off ^ ((off >> 3) & 0x70);
}
__device__ __forceinline__ void ldsm4(uint32_t* r, uint32_t addr) {
    asm volatile("ldmatrix.sync.aligned.m8n8.x4.shared.b16 {%0,%1,%2,%3}, [%4];"
        : "=r"(r[0]), "=r"(r[1]), "=r"(r[2]), "=r"(r[3]) : "r"(addr));
}
__device__ __forceinline__ void mma16816(float* c, const uint32_t* a, const uint2 b) {
    asm volatile("mma.sync.aligned.m16n8k16.row.col.f32.bf16.bf16.f32 "
        "{%0,%1,%2,%3}, {%4,%5,%6,%7}, {%8,%9}, {%0,%1,%2,%3};"
        : "+f"(c[0]), "+f"(c[1]), "+f"(c[2]), "+f"(c[3])
        : "r"(a[0]), "r"(a[1]), "r"(a[2]), "r"(a[3]), "r"(b.x), "r"(b.y));
}
// pack (x,y) -> bf16x2 hi + residual bf16x2 lo
__device__ __forceinline__ void split2(float x, float y, uint32_t& hv, uint32_t& lv) {
    asm("cvt.rn.bf16x2.f32 %0, %1, %2;" : "=r"(hv) : "f"(y), "f"(x));   // high=y, low=x
    float hx = __uint_as_float(hv << 16);
    float hy = __uint_as_float(hv & 0xffff0000u);
    float rx = x - hx, ry = y - hy;
    asm("cvt.rn.bf16x2.f32 %0, %1, %2;" : "=r"(lv) : "f"(ry), "f"(rx));
}

// main kernel dynamic smem layout (bytes)
#define SM_A     0                         // samples hi: 256 rows x 128 B (SW128)
#define SM_ALO   32768                     // samples lo
#define SM_WT    65536                     // float[4][256]
#define SM_IDX   69632                     // int[4][256]
#define SM_TOTAL 73728

// offset-conv kernel smem: A hi + A lo
#define SMO_A     0
#define SMO_ALO   32768
#define SMO_TOTAL 65536

// ---------------------------------------------------------------------------
// prep: fold BN; split w_dcn AND w_off to bf16 hi/lo in mma B-fragment layout.
// B frag (m16n8k16 col): lane holds n = lane>>2, k-pairs 2*(lane&3)+{0,1}
// (reg .x) and +8 (reg .y). k maps to input channel c, n to output o.
// ---------------------------------------------------------------------------
__global__ void prep_kernel(const float* __restrict__ w_dcn,
                            const float* __restrict__ b_dcn,
                            const float* __restrict__ w_off,
                            const float* __restrict__ gamma,
                            const float* __restrict__ beta,
                            const float* __restrict__ run_mean,
                            const float* __restrict__ run_var) {
    int k = blockIdx.x;
    int t = threadIdx.x;
    // main-GEMM B fragments (64 outputs)
    for (int e = t; e < 1024; e += 256) {
        int lane  = e & 31;
        int ntile = (e >> 5) & 7;
        int kstep = e >> 8;
        int o  = ntile*8 + (lane >> 2);
        int c0 = kstep*16 + 2*(lane & 3);
        float w00 = w_dcn[o*576 + (c0  )*9 + k];
        float w01 = w_dcn[o*576 + (c0+1)*9 + k];
        float w10 = w_dcn[o*576 + (c0+8)*9 + k];
        float w11 = w_dcn[o*576 + (c0+9)*9 + k];
        uint32_t h0, l0, h1, l1;
        split2(w00, w01, h0, l0);
        split2(w10, w11, h1, l1);
        int idx = ((k*4 + kstep)*8 + ntile)*32 + lane;
        g_bfrag_hi[idx] = make_uint2(h0, h1);
        g_bfrag_lo[idx] = make_uint2(l0, l1);
    }
    // offset-conv B fragments (18 outputs padded to 24 = 3 ntiles)
    for (int e = t; e < 384; e += 256) {
        int lane  = e & 31;
        int ntile = (e >> 5) % 3;
        int kstep = e / 96;
        int o  = ntile*8 + (lane >> 2);
        int c0 = kstep*16 + 2*(lane & 3);
        float w00 = 0.f, w01 = 0.f, w10 = 0.f, w11 = 0.f;
        if (o < 18) {
            w00 = w_off[o*576 + (c0  )*9 + k];
            w01 = w_off[o*576 + (c0+1)*9 + k];
            w10 = w_off[o*576 + (c0+8)*9 + k];
            w11 = w_off[o*576 + (c0+9)*9 + k];
        }
        uint32_t h0, l0, h1, l1;
        split2(w00, w01, h0, l0);
        split2(w10, w11, h1, l1);
        int idx = ((k*4 + kstep)*3 + ntile)*32 + lane;
        g_bfragO_hi[idx] = make_uint2(h0, h1);
        g_bfragO_lo[idx] = make_uint2(l0, l1);
    }
    if (k == 0 && t < 64) {
        float iv = gamma[t] * rsqrtf(run_var[t] + 1e-5f);
        g_inv[t] = iv;
        g_bias2[t] = b_dcn[t]*iv + beta[t] - run_mean[t]*iv;
    }
}

// ---------------------------------------------------------------------------
// transpose x: [b][c][hw] -> [b][hw][c]
// ---------------------------------------------------------------------------
__global__ __launch_bounds__(256) void transpose_kernel(const float* __restrict__ x) {
    __shared__ float sm[64*65];
    int b   = blockIdx.y;
    int hw0 = blockIdx.x * 64;
    int t   = threadIdx.x;
    const float* xb = x + (size_t)b*64*HWc;
    #pragma unroll
    for (int i = 0; i < 16; i++) {
        int c = i*4 + (t>>6);
        int j = t & 63;
        sm[c*65 + j] = xb[(size_t)c*HWc + hw0 + j];
    }
    __syncthreads();
    float* ob = g_xt + ((size_t)b*HWc + hw0)*64;
    #pragma unroll
    for (int i = 0; i < 16; i++) {
        int hw = i*4 + (t>>6);
        int c  = t & 63;
        ob[hw*64 + c] = sm[c*65 + hw];
    }
}

// ---------------------------------------------------------------------------
// offset conv via tensor cores: implicit GEMM, M=256 px, N=24 (18 used),
// K=576 in 9 tap-phases of K=64. A gathered channel-last from g_xt
// (zero pad), bf16 hi/lo 3-pass. Same fragment machinery as main.
// ---------------------------------------------------------------------------
__global__ __launch_bounds__(256, 2) void offset_mma_kernel(
        const float* __restrict__ b_off) {
    extern __shared__ char smem[];
    const uint32_t sbase = smem_u32(smem);

    const int t    = threadIdx.x;
    const int wid  = t >> 5;
    const int lane = t & 31;
    const int b    = blockIdx.z;
    const int h0   = blockIdx.y * 8;
    const int w0   = blockIdx.x * 32;
    const int sq   = t & 15;
    const int pg   = t >> 4;

    float acc[2][3][4];
    #pragma unroll
    for (int mt = 0; mt < 2; mt++)
        #pragma unroll
        for (int nt = 0; nt < 3; nt++)
            #pragma unroll
            for (int r = 0; r < 4; r++) acc[mt][nt][r] = 0.f;

    const float* xtb = g_xt + (size_t)b*HWc*64;

    const int arow = wid*32 + (lane & 7) + ((lane >> 3) & 1)*8;   // + mt*16
    const int acol = (lane >> 4) * 16;                            // + ks*32

    #pragma unroll 1
    for (int k = 0; k < 9; k++) {
        __syncthreads();   // previous phase's ldmatrix reads done
        const int ky = k/3 - 1, kx = k%3 - 1;

        // build A tile: x[h+ky][w+kx][c-quad], zero-padded, bf16 hi/lo
        #pragma unroll 4
        for (int j = 0; j < 16; j++) {
            int p = pg + 16*j;
            int h = h0 + (p >> 5), w = w0 + (p & 31);
            int hy = h + ky, wx = w + kx;
            float4 v = make_float4(0.f, 0.f, 0.f, 0.f);
            if (hy >= 0 && hy < Hc && wx >= 0 && wx < Wc)
                v = *(const float4*)(xtb + (size_t)(hy*Wc + wx)*64 + sq*4);
            uint2 hv, lv;
            split2(v.x, v.y, hv.x, lv.x);
            split2(v.z, v.w, hv.y, lv.y);
            unsigned sw = sw128((unsigned)(p*128 + sq*8));
            *(uint2*)(smem + SMO_A   + sw) = hv;
            *(uint2*)(smem + SMO_ALO + sw) = lv;
        }
        __syncthreads();

        const uint2* bfh = g_bfragO_hi + (size_t)k*384;
        const uint2* bfl = g_bfragO_lo + (size_t)k*384;
        #pragma unroll
        for (int ks = 0; ks < 4; ks++) {
            uint32_t ah[2][4], al[2][4];
            #pragma unroll
            for (int mt = 0; mt < 2; mt++) {
                unsigned off = sw128((unsigned)((arow + mt*16)*128 + acol + ks*32));
                ldsm4(ah[mt], sbase + SMO_A   + off);
                ldsm4(al[mt], sbase + SMO_ALO + off);
            }
            uint2 bh[3], bl[3];
            #pragma unroll
            for (int nt = 0; nt < 3; nt++) {
                bh[nt] = __ldg(&bfh[(ks*3 + nt)*32 + lane]);
                bl[nt] = __ldg(&bfl[(ks*3 + nt)*32 + lane]);
            }
            #pragma unroll
            for (int mt = 0; mt < 2; mt++)
                #pragma unroll
                for (int nt = 0; nt < 3; nt++) {
                    mma16816(acc[mt][nt], ah[mt], bh[nt]);
                    mma16816(acc[mt][nt], al[mt], bh[nt]);
                    mma16816(acc[mt][nt], ah[mt], bl[nt]);
                }
        }
    }

    // epilogue: add bias, store offsets (only o < 18)
    {
        const int prow = lane >> 2;
        const int ocol = 2*(lane & 3);
        #pragma unroll
        for (int nt = 0; nt < 3; nt++) {
            int o0 = nt*8 + ocol;
            if (o0 < 18) {
                float b0 = b_off[o0], b1 = b_off[o0+1];
                #pragma unroll
                for (int mt = 0; mt < 2; mt++) {
                    #pragma unroll
                    for (int half = 0; half < 2; half++) {
                        int p = wid*32 + mt*16 + prow + half*8;
                        int h = h0 + (p >> 5), w = w0 + (p & 31);
                        g_offset[(((size_t)b*18 + o0  )*Hc + h)*Wc + w] =
                            acc[mt][nt][half*2] + b0;
                        g_offset[(((size_t)b*18 + o0+1)*Hc + h)*Wc + w] =
                            acc[mt][nt][half*2+1] + b1;
                    }
                }
            }
        }
    }
}

// ---------------------------------------------------------------------------
// fused main: bilinear sampling -> bf16 hi/lo A tiles (SW128 smem) ->
// warp-level mma.sync bf16 (3-pass split, fp32 acc) -> BN + ReLU.
// Block = 256 px (8 rows x 32 cols) x 64 o; warp = 32 px x 64 o.
// ---------------------------------------------------------------------------
__global__ __launch_bounds__(256, 2) void main_kernel(float* __restrict__ out) {
    extern __shared__ char smem[];
    const uint32_t sbase = smem_u32(smem);
    float* s_wt  = (float*)(smem + SM_WT);
    int*   s_idx = (int*)(smem + SM_IDX);

    const int t    = threadIdx.x;
    const int wid  = t >> 5;
    const int lane = t & 31;
    const int b    = blockIdx.z;
    const int h0   = blockIdx.y * 8;
    const int w0   = blockIdx.x * 32;
    const int sq   = t & 15;       // sampler channel-quad
    const int pg   = t >> 4;       // sampler pixel phase (0..15)

    float acc[2][8][4];
    #pragma unroll
    for (int mt = 0; mt < 2; mt++)
        #pragma unroll
        for (int nt = 0; nt < 8; nt++)
            #pragma unroll
            for (int r = 0; r < 4; r++) acc[mt][nt][r] = 0.f;

    const float* xtb = g_xt + (size_t)b*HWc*64;

    const int arow = wid*32 + (lane & 7) + ((lane >> 3) & 1)*8;   // + mt*16
    const int acol = (lane >> 4) * 16;                            // + kstep*32

    #pragma unroll 1
    for (int k = 0; k < 9; k++) {
        __syncthreads();   // previous phase's mma reads done

        // per-pixel bilinear metadata (thread t = pixel t)
        {
            int p = t;
            int h = h0 + (p >> 5), w = w0 + (p & 31);
            float oy = g_offset[(((size_t)b*18 + 2*k    )*Hc + h)*Wc + w];
            float ox = g_offset[(((size_t)b*18 + 2*k + 1)*Hc + h)*Wc + w];
            float py = (float)(h + k/3 - 1) + oy;
            float px = (float)(w + k%3 - 1) + ox;
            float y0 = floorf(py), x0 = floorf(px);
            #pragma unroll
            for (int d = 0; d < 4; d++) {
                float iy = y0 + (float)(d >> 1);
                float ix = x0 + (float)(d & 1);
                float wgt = (1.f - fabsf(py - iy)) * (1.f - fabsf(px - ix));
                bool valid = (iy >= 0.f) && (iy <= (float)(Hc-1)) &&
                             (ix >= 0.f) && (ix <= (float)(Wc-1));
                s_wt[d*256 + p] = valid ? wgt : 0.f;
                int iyc = min(max((int)iy, 0), Hc-1);
                int ixc = min(max((int)ix, 0), Wc-1);
                s_idx[d*256 + p] = (iyc*Wc + ixc) * 64;
            }
        }
        __syncthreads();

        // sampling: gather channel-last, split to bf16 hi/lo, store swizzled
        #pragma unroll 4
        for (int j = 0; j < 16; j++) {
            int p = pg + 16*j;
            float ax = 0.f, ay = 0.f, az = 0.f, aw = 0.f;
            #pragma unroll
            for (int d = 0; d < 4; d++) {
                float wg = s_wt[d*256 + p];
                const float4 v = *(const float4*)(xtb + (size_t)s_idx[d*256 + p] + sq*4);
                ax += wg*v.x; ay += wg*v.y; az += wg*v.z; aw += wg*v.w;
            }
            uint2 hv, lv;
            split2(ax, ay, hv.x, lv.x);
            split2(az, aw, hv.y, lv.y);
            unsigned sw = sw128((unsigned)(p*128 + sq*8));
            *(uint2*)(smem + SM_A   + sw) = hv;
            *(uint2*)(smem + SM_ALO + sw) = lv;
        }
        __syncthreads();

        // GEMM: per k-step load A hi/lo frags (ldmatrix) + B hi/lo frags (gmem),
        // issue 3-pass mma
        const uint2* bfh = g_bfrag_hi + (size_t)k*1024;
        const uint2* bfl = g_bfrag_lo + (size_t)k*1024;
        #pragma unroll
        for (int ks = 0; ks < 4; ks++) {
            uint32_t ah[2][4], al[2][4];
            #pragma unroll
            for (int mt = 0; mt < 2; mt++) {
                unsigned off = sw128((unsigned)((arow + mt*16)*128 + acol + ks*32));
                ldsm4(ah[mt], sbase + SM_A   + off);
                ldsm4(al[mt], sbase + SM_ALO + off);
            }
            uint2 bh[8], bl[8];
            #pragma unroll
            for (int nt = 0; nt < 8; nt++) {
                bh[nt] = __ldg(&bfh[(ks*8 + nt)*32 + lane]);
                bl[nt] = __ldg(&bfl[(ks*8 + nt)*32 + lane]);
            }
            #pragma unroll
            for (int mt = 0; mt < 2; mt++)
                #pragma unroll
                for (int nt = 0; nt < 8; nt++) {
                    mma16816(acc[mt][nt], ah[mt], bh[nt]);
                    mma16816(acc[mt][nt], al[mt], bh[nt]);
                    mma16816(acc[mt][nt], ah[mt], bl[nt]);
                }
        }
    }

    // epilogue: BN fold + ReLU, direct stores
    {
        const int prow = lane >> 2;
        const int ocol = 2*(lane & 3);
        #pragma unroll
        for (int nt = 0; nt < 8; nt++) {
            int o0 = nt*8 + ocol;
            float iv0 = g_inv[o0],   bs0 = g_bias2[o0];
            float iv1 = g_inv[o0+1], bs1 = g_bias2[o0+1];
            #pragma unroll
            for (int mt = 0; mt < 2; mt++) {
                #pragma unroll
                for (int half = 0; half < 2; half++) {
                    int p = wid*32 + mt*16 + prow + half*8;
                    int h = h0 + (p >> 5), w = w0 + (p & 31);
                    float* ob = out + ((size_t)b*64*Hc + h)*Wc + w;
                    float y0 = acc[mt][nt][half*2]   * iv0 + bs0;
                    float y1 = acc[mt][nt][half*2+1] * iv1 + bs1;
                    ob[(size_t)o0*HWc]     = fmaxf(y0, 0.f);
                    ob[(size_t)(o0+1)*HWc] = fmaxf(y1, 0.f);
                }
            }
        }
    }
}

// ---------------------------------------------------------------------------
extern "C" void kernel_launch(void* const* d_in, const int* in_sizes, int n_in,
                              void* d_out, int out_size) {
    const float* x        = (const float*)d_in[0];
    const float* w_off    = (const float*)d_in[1];
    const float* b_off    = (const float*)d_in[2];
    const float* w_dcn    = (const float*)d_in[3];
    const float* b_dcn    = (const float*)d_in[4];
    const float* gamma    = (const float*)d_in[5];
    const float* beta     = (const float*)d_in[6];
    const float* run_mean = (const float*)d_in[7];
    const float* run_var  = (const float*)d_in[8];
    float* out = (float*)d_out;

    cudaFuncSetAttribute(main_kernel,
                         cudaFuncAttributeMaxDynamicSharedMemorySize, SM_TOTAL);
    cudaFuncSetAttribute(offset_mma_kernel,
                         cudaFuncAttributeMaxDynamicSharedMemorySize, SMO_TOTAL);

    dim3 grid(Wc/32, Hc/8, Bc);
    prep_kernel<<<9, 256>>>(w_dcn, b_dcn, w_off, gamma, beta, run_mean, run_var);
    transpose_kernel<<<dim3(HWc/64, Bc), 256>>>(x);
    offset_mma_kernel<<<grid, 256, SMO_TOTAL>>>(b_off);
    main_kernel<<<grid, 256, SM_TOTAL>>>(out);
}

// round 8
// speedup vs baseline: 3.9987x; 1.0410x over previous
#include <cuda_runtime.h>
#include <cuda_bf16.h>
#include <cstdint>

#define Bc 8
#define Hc 160
#define Wc 160
#define HWc (Hc*Wc)

typedef unsigned long long ull;

// scratch (no allocations allowed)
__device__ float g_xt[(size_t)Bc*HWc*64];        // x transposed to [b][hw][c]
__device__ uint2 g_bfrag_hi[9*4*8*32];           // main B frags bf16 hi [k][kstep][ntile][lane]
__device__ uint2 g_bfrag_lo[9*4*8*32];           // main B frags bf16 lo
__device__ uint2 g_bfragO_hi[9*4*3*32];          // offset-conv B frags hi
__device__ uint2 g_bfragO_lo[9*4*3*32];          // offset-conv B frags lo
__device__ float g_inv[64];
__device__ float g_bias2[64];

__device__ __forceinline__ uint32_t smem_u32(const void* p) {
    uint32_t a;
    asm("{ .reg .u64 t; cvta.to.shared.u64 t, %1; cvt.u32.u64 %0, t; }" : "=r"(a) : "l"(p));
    return a;
}
__device__ __forceinline__ unsigned sw128(unsigned off) {
    return off ^ ((off >> 3) & 0x70);
}
__device__ __forceinline__ void ldsm4(uint32_t* r, uint32_t addr) {
    asm volatile("ldmatrix.sync.aligned.m8n8.x4.shared.b16 {%0,%1,%2,%3}, [%4];"
        : "=r"(r[0]), "=r"(r[1]), "=r"(r[2]), "=r"(r[3]) : "r"(addr));
}
__device__ __forceinline__ void mma16816(float* c, const uint32_t* a, const uint2 b) {
    asm volatile("mma.sync.aligned.m16n8k16.row.col.f32.bf16.bf16.f32 "
        "{%0,%1,%2,%3}, {%4,%5,%6,%7}, {%8,%9}, {%0,%1,%2,%3};"
        : "+f"(c[0]), "+f"(c[1]), "+f"(c[2]), "+f"(c[3])
        : "r"(a[0]), "r"(a[1]), "r"(a[2]), "r"(a[3]), "r"(b.x), "r"(b.y));
}
// pack (x,y) -> bf16x2
__device__ __forceinline__ uint32_t pack_bf16x2(float x, float y) {
    uint32_t r;
    asm("cvt.rn.bf16x2.f32 %0, %1, %2;" : "=r"(r) : "f"(y), "f"(x));
    return r;
}
// pack (x,y) -> bf16x2 hi + residual bf16x2 lo
__device__ __forceinline__ void split2(float x, float y, uint32_t& hv, uint32_t& lv) {
    asm("cvt.rn.bf16x2.f32 %0, %1, %2;" : "=r"(hv) : "f"(y), "f"(x));
    float hx = __uint_as_float(hv << 16);
    float hy = __uint_as_float(hv & 0xffff0000u);
    float rx = x - hx, ry = y - hy;
    asm("cvt.rn.bf16x2.f32 %0, %1, %2;" : "=r"(lv) : "f"(ry), "f"(rx));
}

// fused kernel dynamic smem layout (bytes)
#define SM_A     0                         // A hi: 256 rows x 128 B (SW128)
#define SM_ALO   32768                     // A lo
#define SM_OFF   65536                     // float[18][256] offsets
#define SM_WT    84992                     // float[2][4][256] meta, double-buffered
#define SM_IDX   93184                     // int[2][4][256]
#define SM_TOTAL 101376

// ---------------------------------------------------------------------------
// prep: fold BN; split w_dcn AND w_off to bf16 hi/lo in mma B-fragment layout.
// ---------------------------------------------------------------------------
__global__ void prep_kernel(const float* __restrict__ w_dcn,
                            const float* __restrict__ b_dcn,
                            const float* __restrict__ w_off,
                            const float* __restrict__ gamma,
                            const float* __restrict__ beta,
                            const float* __restrict__ run_mean,
                            const float* __restrict__ run_var) {
    int k = blockIdx.x;
    int t = threadIdx.x;
    // main-GEMM B fragments (64 outputs)
    for (int e = t; e < 1024; e += 256) {
        int lane  = e & 31;
        int ntile = (e >> 5) & 7;
        int kstep = e >> 8;
        int o  = ntile*8 + (lane >> 2);
        int c0 = kstep*16 + 2*(lane & 3);
        float w00 = w_dcn[o*576 + (c0  )*9 + k];
        float w01 = w_dcn[o*576 + (c0+1)*9 + k];
        float w10 = w_dcn[o*576 + (c0+8)*9 + k];
        float w11 = w_dcn[o*576 + (c0+9)*9 + k];
        uint32_t h0, l0, h1, l1;
        split2(w00, w01, h0, l0);
        split2(w10, w11, h1, l1);
        int idx = ((k*4 + kstep)*8 + ntile)*32 + lane;
        g_bfrag_hi[idx] = make_uint2(h0, h1);
        g_bfrag_lo[idx] = make_uint2(l0, l1);
    }
    // offset-conv B fragments (18 outputs padded to 24 = 3 ntiles)
    for (int e = t; e < 384; e += 256) {
        int lane  = e & 31;
        int ntile = (e >> 5) % 3;
        int kstep = e / 96;
        int o  = ntile*8 + (lane >> 2);
        int c0 = kstep*16 + 2*(lane & 3);
        float w00 = 0.f, w01 = 0.f, w10 = 0.f, w11 = 0.f;
        if (o < 18) {
            w00 = w_off[o*576 + (c0  )*9 + k];
            w01 = w_off[o*576 + (c0+1)*9 + k];
            w10 = w_off[o*576 + (c0+8)*9 + k];
            w11 = w_off[o*576 + (c0+9)*9 + k];
        }
        uint32_t h0, l0, h1, l1;
        split2(w00, w01, h0, l0);
        split2(w10, w11, h1, l1);
        int idx = ((k*4 + kstep)*3 + ntile)*32 + lane;
        g_bfragO_hi[idx] = make_uint2(h0, h1);
        g_bfragO_lo[idx] = make_uint2(l0, l1);
    }
    if (k == 0 && t < 64) {
        float iv = gamma[t] * rsqrtf(run_var[t] + 1e-5f);
        g_inv[t] = iv;
        g_bias2[t] = b_dcn[t]*iv + beta[t] - run_mean[t]*iv;
    }
}

// ---------------------------------------------------------------------------
// transpose x: [b][c][hw] -> [b][hw][c]
// ---------------------------------------------------------------------------
__global__ __launch_bounds__(256) void transpose_kernel(const float* __restrict__ x) {
    __shared__ float sm[64*65];
    int b   = blockIdx.y;
    int hw0 = blockIdx.x * 64;
    int t   = threadIdx.x;
    const float* xb = x + (size_t)b*64*HWc;
    #pragma unroll
    for (int i = 0; i < 16; i++) {
        int c = i*4 + (t>>6);
        int j = t & 63;
        sm[c*65 + j] = xb[(size_t)c*HWc + hw0 + j];
    }
    __syncthreads();
    float* ob = g_xt + ((size_t)b*HWc + hw0)*64;
    #pragma unroll
    for (int i = 0; i < 16; i++) {
        int hw = i*4 + (t>>6);
        int c  = t & 63;
        ob[hw*64 + c] = sm[c*65 + hw];
    }
}

// ---------------------------------------------------------------------------
// fused: [phase 1] offset conv (implicit GEMM, A single-bf16, B hi/lo 2-pass)
// -> offsets in smem; [phase 2] deform bilinear sampling + 3-pass bf16 GEMM
// + BN + ReLU. Block = 256 px (8 rows x 32 cols), 256 threads.
// ---------------------------------------------------------------------------
__global__ __launch_bounds__(256, 2) void fused_kernel(
        const float* __restrict__ b_off,
        float* __restrict__ out) {
    extern __shared__ char smem[];
    const uint32_t sbase = smem_u32(smem);
    float* s_off = (float*)(smem + SM_OFF);   // [18][256]
    float* s_wt  = (float*)(smem + SM_WT);    // [2][4][256]
    int*   s_idx = (int*)(smem + SM_IDX);     // [2][4][256]

    const int t    = threadIdx.x;
    const int wid  = t >> 5;
    const int lane = t & 31;
    const int b    = blockIdx.z;
    const int h0   = blockIdx.y * 8;
    const int w0   = blockIdx.x * 32;
    const int sq   = t & 15;       // sampler channel-quad
    const int pg   = t >> 4;       // sampler pixel phase (0..15)

    const float* xtb = g_xt + (size_t)b*HWc*64;

    // A-frag ldmatrix base coords (constant)
    const int arow = wid*32 + (lane & 7) + ((lane >> 3) & 1)*8;   // + mt*16
    const int acol = (lane >> 4) * 16;                            // + ks*32
    const int prow = lane >> 2;
    const int ocol = 2*(lane & 3);

    // ============================ phase 1: offset conv =====================
    {
        float acc[2][3][4];
        #pragma unroll
        for (int mt = 0; mt < 2; mt++)
            #pragma unroll
            for (int nt = 0; nt < 3; nt++)
                #pragma unroll
                for (int r = 0; r < 4; r++) acc[mt][nt][r] = 0.f;

        #pragma unroll 1
        for (int k = 0; k < 9; k++) {
            __syncthreads();   // A free
            const int ky = k/3 - 1, kx = k%3 - 1;

            // A tile (bf16 hi only): x[h+ky][w+kx][c-quad], zero padded
            #pragma unroll 4
            for (int j = 0; j < 16; j++) {
                int p = pg + 16*j;
                int h = h0 + (p >> 5), w = w0 + (p & 31);
                int hy = h + ky, wx = w + kx;
                float4 v = make_float4(0.f, 0.f, 0.f, 0.f);
                if (hy >= 0 && hy < Hc && wx >= 0 && wx < Wc)
                    v = *(const float4*)(xtb + (size_t)(hy*Wc + wx)*64 + sq*4);
                uint2 hv;
                hv.x = pack_bf16x2(v.x, v.y);
                hv.y = pack_bf16x2(v.z, v.w);
                *(uint2*)(smem + SM_A + sw128((unsigned)(p*128 + sq*8))) = hv;
            }
            __syncthreads();

            const uint2* bfh = g_bfragO_hi + (size_t)k*384;
            const uint2* bfl = g_bfragO_lo + (size_t)k*384;
            #pragma unroll
            for (int ks = 0; ks < 4; ks++) {
                uint32_t ah[2][4];
                #pragma unroll
                for (int mt = 0; mt < 2; mt++) {
                    unsigned off = sw128((unsigned)((arow + mt*16)*128 + acol + ks*32));
                    ldsm4(ah[mt], sbase + SM_A + off);
                }
                uint2 bh[3], bl[3];
                #pragma unroll
                for (int nt = 0; nt < 3; nt++) {
                    bh[nt] = __ldg(&bfh[(ks*3 + nt)*32 + lane]);
                    bl[nt] = __ldg(&bfl[(ks*3 + nt)*32 + lane]);
                }
                #pragma unroll
                for (int mt = 0; mt < 2; mt++)
                    #pragma unroll
                    for (int nt = 0; nt < 3; nt++) {
                        mma16816(acc[mt][nt], ah[mt], bh[nt]);
                        mma16816(acc[mt][nt], ah[mt], bl[nt]);
                    }
            }
        }

        // epilogue: offsets (+bias) into smem [oc][p]
        #pragma unroll
        for (int nt = 0; nt < 3; nt++) {
            int o0 = nt*8 + ocol;
            if (o0 < 18) {
                float bo0 = b_off[o0], bo1 = b_off[o0+1];
                #pragma unroll
                for (int mt = 0; mt < 2; mt++) {
                    #pragma unroll
                    for (int half = 0; half < 2; half++) {
                        int p = wid*32 + mt*16 + prow + half*8;
                        s_off[o0*256 + p]     = acc[mt][nt][half*2]   + bo0;
                        s_off[(o0+1)*256 + p] = acc[mt][nt][half*2+1] + bo1;
                    }
                }
            }
        }
    }
    __syncthreads();   // s_off complete

    // ============================ phase 2: deform GEMM =====================
    float acc[2][8][4];
    #pragma unroll
    for (int mt = 0; mt < 2; mt++)
        #pragma unroll
        for (int nt = 0; nt < 8; nt++)
            #pragma unroll
            for (int r = 0; r < 4; r++) acc[mt][nt][r] = 0.f;

    // meta(k) compute for pixel t into buffer k&1
    const int mh = h0 + (t >> 5), mw = w0 + (t & 31);
    #define COMPUTE_META(k) do {                                              \
        int buf = (k) & 1;                                                    \
        float oy = s_off[(2*(k)  )*256 + t];                                  \
        float ox = s_off[(2*(k)+1)*256 + t];                                  \
        float py = (float)(mh + (k)/3 - 1) + oy;                              \
        float px = (float)(mw + (k)%3 - 1) + ox;                              \
        float y0 = floorf(py), x0 = floorf(px);                               \
        _Pragma("unroll")                                                     \
        for (int d = 0; d < 4; d++) {                                         \
            float iy = y0 + (float)(d >> 1);                                  \
            float ix = x0 + (float)(d & 1);                                   \
            float wgt = (1.f - fabsf(py - iy)) * (1.f - fabsf(px - ix));      \
            bool valid = (iy >= 0.f) && (iy <= (float)(Hc-1)) &&              \
                         (ix >= 0.f) && (ix <= (float)(Wc-1));                \
            s_wt[buf*1024 + d*256 + t] = valid ? wgt : 0.f;                   \
            int iyc = min(max((int)iy, 0), Hc-1);                             \
            int ixc = min(max((int)ix, 0), Wc-1);                             \
            s_idx[buf*1024 + d*256 + t] = (iyc*Wc + ixc) * 64;                \
        }                                                                     \
    } while (0)

    COMPUTE_META(0);

    #pragma unroll 1
    for (int k = 0; k < 9; k++) {
        __syncthreads();   // A free (prev mma done) + meta[k] ready
        const int buf = k & 1;

        // sampling: gather channel-last, split to bf16 hi/lo, store swizzled
        #pragma unroll 4
        for (int j = 0; j < 16; j++) {
            int p = pg + 16*j;
            float ax = 0.f, ay = 0.f, az = 0.f, aw = 0.f;
            #pragma unroll
            for (int d = 0; d < 4; d++) {
                float wg = s_wt[buf*1024 + d*256 + p];
                const float4 v = *(const float4*)(xtb + (size_t)s_idx[buf*1024 + d*256 + p] + sq*4);
                ax += wg*v.x; ay += wg*v.y; az += wg*v.z; aw += wg*v.w;
            }
            uint2 hv, lv;
            split2(ax, ay, hv.x, lv.x);
            split2(az, aw, hv.y, lv.y);
            unsigned sw = sw128((unsigned)(p*128 + sq*8));
            *(uint2*)(smem + SM_A   + sw) = hv;
            *(uint2*)(smem + SM_ALO + sw) = lv;
        }
        __syncthreads();   // A ready

        // overlap: meta for k+1 (other buffer) hidden under mma issue
        if (k < 8) COMPUTE_META(k + 1);

        // GEMM: per k-step load A hi/lo frags + B hi/lo frags, 3-pass mma
        const uint2* bfh = g_bfrag_hi + (size_t)k*1024;
        const uint2* bfl = g_bfrag_lo + (size_t)k*1024;
        #pragma unroll
        for (int ks = 0; ks < 4; ks++) {
            uint32_t ah[2][4], al[2][4];
            #pragma unroll
            for (int mt = 0; mt < 2; mt++) {
                unsigned off = sw128((unsigned)((arow + mt*16)*128 + acol + ks*32));
                ldsm4(ah[mt], sbase + SM_A   + off);
                ldsm4(al[mt], sbase + SM_ALO + off);
            }
            uint2 bh[8], bl[8];
            #pragma unroll
            for (int nt = 0; nt < 8; nt++) {
                bh[nt] = __ldg(&bfh[(ks*8 + nt)*32 + lane]);
                bl[nt] = __ldg(&bfl[(ks*8 + nt)*32 + lane]);
            }
            #pragma unroll
            for (int mt = 0; mt < 2; mt++)
                #pragma unroll
                for (int nt = 0; nt < 8; nt++) {
                    mma16816(acc[mt][nt], ah[mt], bh[nt]);
                    mma16816(acc[mt][nt], al[mt], bh[nt]);
                    mma16816(acc[mt][nt], ah[mt], bl[nt]);
                }
        }
    }

    // epilogue: BN fold + ReLU, direct stores
    #pragma unroll
    for (int nt = 0; nt < 8; nt++) {
        int o0 = nt*8 + ocol;
        float iv0 = g_inv[o0],   bs0 = g_bias2[o0];
        float iv1 = g_inv[o0+1], bs1 = g_bias2[o0+1];
        #pragma unroll
        for (int mt = 0; mt < 2; mt++) {
            #pragma unroll
            for (int half = 0; half < 2; half++) {
                int p = wid*32 + mt*16 + prow + half*8;
                int h = h0 + (p >> 5), w = w0 + (p & 31);
                float* ob = out + ((size_t)b*64*Hc + h)*Wc + w;
                float y0 = acc[mt][nt][half*2]   * iv0 + bs0;
                float y1 = acc[mt][nt][half*2+1] * iv1 + bs1;
                ob[(size_t)o0*HWc]     = fmaxf(y0, 0.f);
                ob[(size_t)(o0+1)*HWc] = fmaxf(y1, 0.f);
            }
        }
    }
}

// ---------------------------------------------------------------------------
extern "C" void kernel_launch(void* const* d_in, const int* in_sizes, int n_in,
                              void* d_out, int out_size) {
    const float* x        = (const float*)d_in[0];
    const float* w_off    = (const float*)d_in[1];
    const float* b_off    = (const float*)d_in[2];
    const float* w_dcn    = (const float*)d_in[3];
    const float* b_dcn    = (const float*)d_in[4];
    const float* gamma    = (const float*)d_in[5];
    const float* beta     = (const float*)d_in[6];
    const float* run_mean = (const float*)d_in[7];
    const float* run_var  = (const float*)d_in[8];
    float* out = (float*)d_out;

    cudaFuncSetAttribute(fused_kernel,
                         cudaFuncAttributeMaxDynamicSharedMemorySize, SM_TOTAL);

    dim3 grid(Wc/32, Hc/8, Bc);
    prep_kernel<<<9, 256>>>(w_dcn, b_dcn, w_off, gamma, beta, run_mean, run_var);
    transpose_kernel<<<dim3(HWc/64, Bc), 256>>>(x);
    fused_kernel<<<grid, 256, SM_TOTAL>>>(b_off, out);
}